// round 8
// baseline (speedup 1.0000x reference)
#include <cuda_runtime.h>
#include <cuda_fp16.h>

// ROI Align via fp16 NHWC relayout — fused producer/consumer kernel.
// Single grid, chunk-interleaved block roles:
//   chunk k (batch b = k>>1, channel-half h = k&1):
//     3800 transpose blocks  (NCHW fp32 -> NHWC fp16 scratch, DRAM-bound)
//      512 ROI blocks        (bilinear gather + pool, L1/issue-bound)
// ROI blocks of chunk k spin on done[k] until its 3800 producers fenced.
// In-order dispatch + producers-have-lower-bids => deadlock-free; the two
// roles overlap on disjoint resources (DRAM vs L1/issue).

#define NCH   256
#define FH    200
#define FW    304
#define HW    (FH*FW)        // 60800
#define POUT  7
#define OPP   49
#define S14   14
#define CHB   128            // channels per chunk / ROI block
#define SMP   133            // staging pitch (floats), 133 mod 32 = 5

#define TBLK  3800           // transpose blocks per chunk (1900 hw-tiles x 2)
#define RBLK  512            // ROI blocks per chunk
#define CBLK  (TBLK + RBLK)  // 4312
#define NCHUNK 4

// dynamic smem layout (bytes):
//   [0,448)        ROI axis tables   | transpose reuses [0, 8320) as tile
//   [448,3584)     swt (196 x uint4)
//   [3584,6720)    soff (196 x int4)
//   [6720,32788)   staging sm[49*133]
#define SMEM_BYTES 32800

__device__ unsigned int g_nh[(size_t)2 * HW * (NCH/2)];   // fp16x2 NHWC, 62 MB
__device__ int g_done[NCHUNK];

__global__ void reset_done()
{
    if (threadIdx.x < NCHUNK) g_done[threadIdx.x] = 0;
}

__device__ __forceinline__ void axis_prep(float t, int size,
                                          int& lo, int& hi, float& frac,
                                          float& valid)
{
    valid = (t > -1.0f && t < (float)size) ? 1.0f : 0.0f;
    float tc  = (t < 0.0f) ? 0.0f : t;
    float low = floorf(tc);
    if (low >= (float)(size - 1)) {
        lo = size - 1; hi = size - 1; frac = 0.0f;
    } else {
        lo = (int)low; hi = lo + 1; frac = tc - low;
    }
}

__device__ __forceinline__ __half2 h2(unsigned int u)
{
    return *reinterpret_cast<const __half2*>(&u);
}

__device__ __forceinline__ unsigned int rep_h2(float f)
{
    __half2 h = __float2half2_rn(f);
    return *reinterpret_cast<unsigned int*>(&h);
}

__global__ void __launch_bounds__(256, 5)
fused_roi(const float* __restrict__ feat,
          const float* __restrict__ boxes,
          float* __restrict__ out)
{
    extern __shared__ char smx[];
    const int bid   = blockIdx.x;
    const int chunk = bid / CBLK;
    const int local = bid - chunk * CBLK;
    const int b     = chunk >> 1;
    const int chalf = chunk & 1;
    const int tid   = threadIdx.x;

    if (local < TBLK) {
        // ---------------- transpose role ----------------
        float (*tile)[65] = (float(*)[65])smx;
        const int hw0 = (local % 1900) * 32;
        const int cy  = local / 1900;                 // 0..1
        const int c0  = chalf * CHB + cy * 64;
        const int tx  = tid & 31;
        const int ty  = tid >> 5;                     // 0..7

        const float* src = feat + (size_t)(b * NCH + c0) * HW + hw0;
#pragma unroll
        for (int k = 0; k < 8; k++)
            tile[tx][ty + 8*k] = src[(size_t)(ty + 8*k) * HW + tx];
        __syncthreads();

        unsigned int* dst = g_nh + (size_t)(b * HW + hw0) * (NCH/2) + (c0 >> 1);
#pragma unroll
        for (int i = 0; i < 4; i++) {
            int hw = i*8 + ty;
            __half2 h = __floats2half2_rn(tile[hw][2*tx], tile[hw][2*tx + 1]);
            dst[(size_t)hw * (NCH/2) + tx] = *(unsigned int*)&h;
        }
        __syncthreads();
        if (tid == 0) {
            __threadfence();                          // release scratch writes
            atomicAdd(&g_done[chunk], 1);
        }
        return;
    }

    // ---------------- ROI role ----------------
    int*   sxl = (int*)smx;            // [14]
    int*   sxh = sxl + S14;
    int*   syl = sxh + S14;
    int*   syh = syl + S14;
    float* sfx = (float*)(syh + S14);
    float* svx = sfx + S14;
    float* sfy = svx + S14;
    float* svy = sfy + S14;
    uint4* swt  = (uint4*)(smx + 448);   // [196]
    int4*  soff = (int4*)(smx + 3584);   // [196]
    float* sm   = (float*)(smx + 6720);  // [49*133]

    const int r    = b * 512 + (local - TBLK);
    const int lane = tid & 31;
    const int w    = tid >> 5;

    // metadata can be built while producers still run (reads boxes only)
    if (tid < 32) {
        float x1 = boxes[r*4+0] * 0.25f;
        float y1 = boxes[r*4+1] * 0.25f;
        float x2 = boxes[r*4+2] * 0.25f;
        float y2 = boxes[r*4+3] * 0.25f;
        float bw = fmaxf(x2 - x1, 1.0f) * (1.0f/POUT);
        float bh = fmaxf(y2 - y1, 1.0f) * (1.0f/POUT);

        if (tid < S14) {
            float xs = x1 + ((float)tid + 0.5f) * 0.5f * bw;
            int lo, hi; float fr, vd;
            axis_prep(xs, FW, lo, hi, fr, vd);
            sxl[tid] = lo * (NCH/4);          // *64 uint2 per texel
            sxh[tid] = hi * (NCH/4);
            sfx[tid] = fr;  svx[tid] = vd;
        } else if (tid >= 16 && tid < 16 + S14) {
            int i = tid - 16;
            float ys = y1 + ((float)i + 0.5f) * 0.5f * bh;
            int lo, hi; float fr, vd;
            axis_prep(ys, FH, lo, hi, fr, vd);
            syl[i] = lo * FW * (NCH/4);
            syh[i] = hi * FW * (NCH/4);
            sfy[i] = fr;  svy[i] = vd;
        }
    }
    __syncthreads();

    if (tid < 196) {
        int iy = tid / S14;
        int ix = tid - iy * S14;
        float fy = sfy[iy], hy = 1.0f - fy;
        float fx = sfx[ix], hx = 1.0f - fx;
        float vv = svy[iy] * svx[ix];
        swt[tid]  = make_uint4(rep_h2(vv*hy*hx), rep_h2(vv*hy*fx),
                               rep_h2(vv*fy*hx), rep_h2(vv*fy*fx));
        int yl = syl[iy], yh = syh[iy];
        int xl = sxl[ix], xh = sxh[ix];
        soff[tid] = make_int4(yl + xl, yl + xh, yh + xl, yh + xh);
    }

    // wait for this chunk's producers
    if (tid == 0) {
        volatile int* done = g_done;
        while (done[chunk] < TBLK) __nanosleep(128);
    }
    __syncthreads();
    __threadfence();                    // acquire scratch writes

    const uint2* __restrict__ base =
        (const uint2*)g_nh + (size_t)b * HW * (NCH/4) + chalf * 32 + lane;

    for (int p = w; p < OPP; p += 8) {
        int ph = p / POUT, pw = p - ph * POUT;
        int t00 = (2*ph) * S14 + 2*pw;
        float f0 = 0.f, f1 = 0.f, f2 = 0.f, f3 = 0.f;
#pragma unroll
        for (int sy = 0; sy < 2; sy++) {
#pragma unroll
            for (int sx = 0; sx < 2; sx++) {
                int   idx = t00 + sy * S14 + sx;
                int4  o   = soff[idx];
                uint4 wt  = swt[idx];

                uint2 q00 = __ldg(base + o.x);
                uint2 q01 = __ldg(base + o.y);
                uint2 q10 = __ldg(base + o.z);
                uint2 q11 = __ldg(base + o.w);

                __half2 t0 = __hmul2(h2(wt.x), h2(q00.x));
                __half2 t1 = __hmul2(h2(wt.x), h2(q00.y));
                t0 = __hfma2(h2(wt.y), h2(q01.x), t0);
                t1 = __hfma2(h2(wt.y), h2(q01.y), t1);
                t0 = __hfma2(h2(wt.z), h2(q10.x), t0);
                t1 = __hfma2(h2(wt.z), h2(q10.y), t1);
                t0 = __hfma2(h2(wt.w), h2(q11.x), t0);
                t1 = __hfma2(h2(wt.w), h2(q11.y), t1);

                float2 a0 = __half22float2(t0);
                float2 a1 = __half22float2(t1);
                f0 += a0.x; f1 += a0.y;
                f2 += a1.x; f3 += a1.y;
            }
        }
        // permuted staging: channel 4*lane+j -> offset j*32 + lane
        float* d = sm + p * SMP + lane;
        d[0]  = f0 * 0.25f;
        d[32] = f1 * 0.25f;
        d[64] = f2 * 0.25f;
        d[96] = f3 * 0.25f;
    }
    __syncthreads();

    // flush: this block owns out[r, chalf*128 .. +128, :] = 6272 contiguous
    float* dst = out + (size_t)r * (NCH * OPP) + (size_t)chalf * (CHB * OPP);
    for (int t = tid; t < CHB * OPP; t += 256) {
        int c = t / OPP;                 // local channel 0..127
        int p = t - c * OPP;
        dst[t] = sm[p * SMP + (c & 3) * 32 + (c >> 2)];
    }
}

extern "C" void kernel_launch(void* const* d_in, const int* in_sizes, int n_in,
                              void* d_out, int out_size)
{
    const float* feat  = (const float*)d_in[0];
    const float* boxes = (const float*)d_in[1];
    float* out = (float*)d_out;

    reset_done<<<1, 32>>>();
    fused_roi<<<NCHUNK * CBLK, 256, SMEM_BYTES>>>(feat, boxes, out);
}

// round 9
// speedup vs baseline: 1.0763x; 1.0763x over previous
#include <cuda_runtime.h>
#include <cuda_fp16.h>

// ROI Align via fp16 NHWC relayout — fused producer/consumer kernel with
// INTERLEAVED bid layout:
//   [ T0 (3800) | T1⊕R0 (4312) | T2⊕R1 | T3⊕R2 | R3 (512) ]
// In each mixed region, 1 ROI block per 8 transpose blocks (R at v%8==7 for
// v<4096) -> residency stays ~70% transpose / 30% ROI, so the DRAM-bound
// transpose keeps its bandwidth while ROI drains on L1/issue.
// Consumers of chunk k spin (nanosleep) until all 3800 producers of chunk k
// fenced; producers always have lower bids -> deadlock-free.

#define NCH   256
#define FH    200
#define FW    304
#define HW    (FH*FW)        // 60800
#define POUT  7
#define OPP   49
#define S14   14
#define CHB   128            // channels per chunk
#define SMP   133            // staging pitch, 133 mod 32 = 5

#define TBLK  3800           // transpose blocks per chunk
#define RBLK  512            // ROI blocks per chunk
#define MIXB  (TBLK + RBLK)  // 4312
#define NCHUNK 4
#define GRID_TOT (TBLK + 3*MIXB + RBLK)   // 17248

// dynamic smem union:
//  T role: tile[32][65] floats (8320 B)
//  R role: [0,448) axis tables | [448,3584) swt | [3584,6720) soff
//          [6720,32788) staging 49*133 floats
#define SMEM_BYTES 32800

__device__ unsigned int g_nh[(size_t)2 * HW * (NCH/2)];   // fp16x2 NHWC, 62 MB
__device__ int g_done[NCHUNK];

__global__ void reset_done()
{
    if (threadIdx.x < NCHUNK) g_done[threadIdx.x] = 0;
}

__device__ __forceinline__ void axis_prep(float t, int size,
                                          int& lo, int& hi, float& frac,
                                          float& valid)
{
    valid = (t > -1.0f && t < (float)size) ? 1.0f : 0.0f;
    float tc  = (t < 0.0f) ? 0.0f : t;
    float low = floorf(tc);
    if (low >= (float)(size - 1)) {
        lo = size - 1; hi = size - 1; frac = 0.0f;
    } else {
        lo = (int)low; hi = lo + 1; frac = tc - low;
    }
}

__device__ __forceinline__ __half2 h2(unsigned int u)
{
    return *reinterpret_cast<const __half2*>(&u);
}

__device__ __forceinline__ unsigned int rep_h2(float f)
{
    __half2 h = __float2half2_rn(f);
    return *reinterpret_cast<unsigned int*>(&h);
}

__global__ void __launch_bounds__(256, 5)
fused_roi(const float* __restrict__ feat,
          const float* __restrict__ boxes,
          float* __restrict__ out)
{
    extern __shared__ char smx[];
    const int bid = blockIdx.x;
    const int tid = threadIdx.x;

    // ---- bid -> (role, chunk, idx) ----
    int roleT, chunk, idx;
    if (bid < TBLK) {
        roleT = 1; chunk = 0; idx = bid;
    } else {
        int u   = bid - TBLK;
        int reg = u / MIXB;
        if (reg < 3) {
            int v = u - reg * MIXB;
            if (v < 8 * RBLK) {                       // 4096
                if ((v & 7) == 7) { roleT = 0; chunk = reg;     idx = v >> 3; }
                else              { roleT = 1; chunk = reg + 1; idx = v - ((v + 1) >> 3); }
            } else {
                roleT = 1; chunk = reg + 1; idx = v - RBLK;
            }
        } else {
            roleT = 0; chunk = 3; idx = u - 3 * MIXB;
        }
    }

    const int b     = (roleT ? chunk : chunk) >> 1;
    const int chalf = chunk & 1;

    if (roleT) {
        // ---------------- transpose role ----------------
        float (*tile)[65] = (float(*)[65])smx;
        const int hw0 = (idx % 1900) * 32;
        const int cy  = idx / 1900;                   // 0..1
        const int c0  = chalf * CHB + cy * 64;
        const int tx  = tid & 31;
        const int ty  = tid >> 5;                     // 0..7

        const float* src = feat + (size_t)(b * NCH + c0) * HW + hw0;
#pragma unroll
        for (int k = 0; k < 8; k++)
            tile[tx][ty + 8*k] = __ldcs(&src[(size_t)(ty + 8*k) * HW + tx]);
        __syncthreads();

        unsigned int* dst = g_nh + (size_t)(b * HW + hw0) * (NCH/2) + (c0 >> 1);
#pragma unroll
        for (int i = 0; i < 4; i++) {
            int hw = i*8 + ty;
            __half2 h = __floats2half2_rn(tile[hw][2*tx], tile[hw][2*tx + 1]);
            dst[(size_t)hw * (NCH/2) + tx] = *(unsigned int*)&h;
        }
        __syncthreads();
        if (tid == 0) {
            __threadfence();                          // release scratch writes
            atomicAdd(&g_done[chunk], 1);
        }
        return;
    }

    // ---------------- ROI role ----------------
    int*   sxl = (int*)smx;            // [14]
    int*   sxh = sxl + S14;
    int*   syl = sxh + S14;
    int*   syh = syl + S14;
    float* sfx = (float*)(syh + S14);
    float* svx = sfx + S14;
    float* sfy = svx + S14;
    float* svy = sfy + S14;
    uint4* swt  = (uint4*)(smx + 448);   // [196]
    int4*  soff = (int4*)(smx + 3584);   // [196]
    float* sm   = (float*)(smx + 6720);  // [49*133]

    const int r    = b * 512 + idx;
    const int lane = tid & 31;
    const int w    = tid >> 5;

    // metadata (reads boxes only; runs while producers work)
    if (tid < 32) {
        float x1 = boxes[r*4+0] * 0.25f;
        float y1 = boxes[r*4+1] * 0.25f;
        float x2 = boxes[r*4+2] * 0.25f;
        float y2 = boxes[r*4+3] * 0.25f;
        float bw = fmaxf(x2 - x1, 1.0f) * (1.0f/POUT);
        float bh = fmaxf(y2 - y1, 1.0f) * (1.0f/POUT);

        if (tid < S14) {
            float xs = x1 + ((float)tid + 0.5f) * 0.5f * bw;
            int lo, hi; float fr, vd;
            axis_prep(xs, FW, lo, hi, fr, vd);
            sxl[tid] = lo * (NCH/4);          // *64 uint2 per texel
            sxh[tid] = hi * (NCH/4);
            sfx[tid] = fr;  svx[tid] = vd;
        } else if (tid >= 16 && tid < 16 + S14) {
            int i = tid - 16;
            float ys = y1 + ((float)i + 0.5f) * 0.5f * bh;
            int lo, hi; float fr, vd;
            axis_prep(ys, FH, lo, hi, fr, vd);
            syl[i] = lo * FW * (NCH/4);
            syh[i] = hi * FW * (NCH/4);
            sfy[i] = fr;  svy[i] = vd;
        }
    }
    __syncthreads();

    if (tid < 196) {
        int iy = tid / S14;
        int ix = tid - iy * S14;
        float fy = sfy[iy], hy = 1.0f - fy;
        float fx = sfx[ix], hx = 1.0f - fx;
        float vv = svy[iy] * svx[ix];
        swt[tid]  = make_uint4(rep_h2(vv*hy*hx), rep_h2(vv*hy*fx),
                               rep_h2(vv*fy*hx), rep_h2(vv*fy*fx));
        int yl = syl[iy], yh = syh[iy];
        int xl = sxl[ix], xh = sxh[ix];
        soff[tid] = make_int4(yl + xl, yl + xh, yh + xl, yh + xh);
    }

    // wait for this chunk's producers
    if (tid == 0) {
        volatile int* done = g_done;
        while (done[chunk] < TBLK) __nanosleep(64);
    }
    __syncthreads();
    __threadfence();                    // acquire scratch writes

    const uint2* __restrict__ base =
        (const uint2*)g_nh + (size_t)b * HW * (NCH/4) + chalf * 32 + lane;

    for (int p = w; p < OPP; p += 8) {
        int ph = p / POUT, pw = p - ph * POUT;
        int t00 = (2*ph) * S14 + 2*pw;
        float f0 = 0.f, f1 = 0.f, f2 = 0.f, f3 = 0.f;
#pragma unroll
        for (int sy = 0; sy < 2; sy++) {
#pragma unroll
            for (int sx = 0; sx < 2; sx++) {
                int   tix = t00 + sy * S14 + sx;
                int4  o   = soff[tix];
                uint4 wt  = swt[tix];

                uint2 q00 = __ldg(base + o.x);
                uint2 q01 = __ldg(base + o.y);
                uint2 q10 = __ldg(base + o.z);
                uint2 q11 = __ldg(base + o.w);

                __half2 t0 = __hmul2(h2(wt.x), h2(q00.x));
                __half2 t1 = __hmul2(h2(wt.x), h2(q00.y));
                t0 = __hfma2(h2(wt.y), h2(q01.x), t0);
                t1 = __hfma2(h2(wt.y), h2(q01.y), t1);
                t0 = __hfma2(h2(wt.z), h2(q10.x), t0);
                t1 = __hfma2(h2(wt.z), h2(q10.y), t1);
                t0 = __hfma2(h2(wt.w), h2(q11.x), t0);
                t1 = __hfma2(h2(wt.w), h2(q11.y), t1);

                float2 a0 = __half22float2(t0);
                float2 a1 = __half22float2(t1);
                f0 += a0.x; f1 += a0.y;
                f2 += a1.x; f3 += a1.y;
            }
        }
        // permuted staging: channel 4*lane+j -> offset j*32 + lane
        float* d = sm + p * SMP + lane;
        d[0]  = f0 * 0.25f;
        d[32] = f1 * 0.25f;
        d[64] = f2 * 0.25f;
        d[96] = f3 * 0.25f;
    }
    __syncthreads();

    // flush: out[r, chalf*128 .. +128, :] = 6272 contiguous floats, streamed
    float* dst = out + (size_t)r * (NCH * OPP) + (size_t)chalf * (CHB * OPP);
    for (int t = tid; t < CHB * OPP; t += 256) {
        int c = t / OPP;                 // local channel 0..127
        int p = t - c * OPP;
        __stcs(&dst[t], sm[p * SMP + (c & 3) * 32 + (c >> 2)]);
    }
}

extern "C" void kernel_launch(void* const* d_in, const int* in_sizes, int n_in,
                              void* d_out, int out_size)
{
    const float* feat  = (const float*)d_in[0];
    const float* boxes = (const float*)d_in[1];
    float* out = (float*)d_out;

    reset_done<<<1, 32>>>();
    fused_roi<<<GRID_TOT, 256, SMEM_BYTES>>>(feat, boxes, out);
}

// round 10
// speedup vs baseline: 1.2867x; 1.1955x over previous
#include <cuda_runtime.h>
#include <cuda_fp16.h>

// ROI Align via fp16 NHWC relayout (two-kernel, sequential — best structure).
//  Pass 1: NCHW fp32 (2,256,200,304) -> NHWC fp16 scratch (62 MB), ldcs reads.
//  Pass 2: block = (ROI, channel-half). 8 warps; warp = output position;
//          lane = 4 channels (uint2). Per-ROI weight/offset tables in smem;
//          half2 corner math, fp32 accumulation across subsamples.
//          Conflict-free permuted staging; stcs output flush. 6 blocks/SM.

#define NCH   256
#define FH    200
#define FW    304
#define HW    (FH*FW)        // 60800
#define POUT  7
#define OPP   49
#define S14   14
#define CHB   128            // channels per ROI block
#define SMP   133            // staging pitch (floats), 133 mod 32 = 5

__device__ unsigned int g_nh[(size_t)2 * HW * (NCH/2)];   // fp16x2 NHWC, 62 MB

// ---------------- Pass 1: NCHW fp32 -> NHWC fp16 ----------------
__global__ void __launch_bounds__(256)
to_nhwc_h(const float* __restrict__ in)
{
    __shared__ float tile[32][65];
    const int b   = blockIdx.z;
    const int c0  = blockIdx.y * 64;
    const int hw0 = blockIdx.x * 32;
    const int tx  = threadIdx.x;            // 0..31 (hw)
    const int ty  = threadIdx.y;            // 0..7  (c)

    const float* src = in + (size_t)(b * NCH + c0) * HW + hw0;
#pragma unroll
    for (int k = 0; k < 8; k++)
        tile[tx][ty + 8*k] = __ldcs(&src[(size_t)(ty + 8*k) * HW + tx]);
    __syncthreads();

    unsigned int* dst = g_nh + (size_t)(b * HW + hw0) * (NCH/2) + (c0 >> 1);
#pragma unroll
    for (int i = 0; i < 4; i++) {
        int hw = i*8 + ty;
        __half2 h = __floats2half2_rn(tile[hw][2*tx], tile[hw][2*tx + 1]);
        dst[(size_t)hw * (NCH/2) + tx] = *(unsigned int*)&h;
    }
}

// ---------------- Pass 2 ----------------
__device__ __forceinline__ void axis_prep(float t, int size,
                                          int& lo, int& hi, float& frac,
                                          float& valid)
{
    valid = (t > -1.0f && t < (float)size) ? 1.0f : 0.0f;
    float tc  = (t < 0.0f) ? 0.0f : t;
    float low = floorf(tc);
    if (low >= (float)(size - 1)) {
        lo = size - 1; hi = size - 1; frac = 0.0f;
    } else {
        lo = (int)low; hi = lo + 1; frac = tc - low;
    }
}

__device__ __forceinline__ __half2 h2(unsigned int u)
{
    return *reinterpret_cast<const __half2*>(&u);
}

__device__ __forceinline__ unsigned int rep_h2(float f)
{
    __half2 h = __float2half2_rn(f);
    return *reinterpret_cast<unsigned int*>(&h);
}

__global__ void __launch_bounds__(256, 6)
roi_align_h2t(const float* __restrict__ boxes,
              float* __restrict__ out)
{
    __shared__ int   sxl[S14], sxh[S14], syl[S14], syh[S14];  // uint2-granular
    __shared__ float sfx[S14], svx[S14], sfy[S14], svy[S14];
    __shared__ uint4 swt[196];          // 4 replicated-half2 corner weights
    __shared__ int4  soff[196];         // 4 combined corner offsets
    __shared__ float sm[OPP * SMP];     // 26.1 KB staging (permuted layout)

    const int r     = blockIdx.x;
    const int chalf = blockIdx.y;
    const int b     = r >> 9;                // 512 boxes per batch
    const int tid   = threadIdx.x;
    const int lane  = tid & 31;
    const int w     = tid >> 5;

    if (tid < 32) {
        float x1 = boxes[r*4+0] * 0.25f;
        float y1 = boxes[r*4+1] * 0.25f;
        float x2 = boxes[r*4+2] * 0.25f;
        float y2 = boxes[r*4+3] * 0.25f;
        float bw = fmaxf(x2 - x1, 1.0f) * (1.0f/POUT);
        float bh = fmaxf(y2 - y1, 1.0f) * (1.0f/POUT);

        if (tid < S14) {
            float xs = x1 + ((float)tid + 0.5f) * 0.5f * bw;
            int lo, hi; float fr, vd;
            axis_prep(xs, FW, lo, hi, fr, vd);
            sxl[tid] = lo * (NCH/4);          // *64 uint2 per texel
            sxh[tid] = hi * (NCH/4);
            sfx[tid] = fr;  svx[tid] = vd;
        } else if (tid >= 16 && tid < 16 + S14) {
            int i = tid - 16;
            float ys = y1 + ((float)i + 0.5f) * 0.5f * bh;
            int lo, hi; float fr, vd;
            axis_prep(ys, FH, lo, hi, fr, vd);
            syl[i] = lo * FW * (NCH/4);
            syh[i] = hi * FW * (NCH/4);
            sfy[i] = fr;  svy[i] = vd;
        }
    }
    __syncthreads();

    if (tid < 196) {
        int iy = tid / S14;
        int ix = tid - iy * S14;
        float fy = sfy[iy], hy = 1.0f - fy;
        float fx = sfx[ix], hx = 1.0f - fx;
        float vv = svy[iy] * svx[ix];
        swt[tid]  = make_uint4(rep_h2(vv*hy*hx), rep_h2(vv*hy*fx),
                               rep_h2(vv*fy*hx), rep_h2(vv*fy*fx));
        int yl = syl[iy], yh = syh[iy];
        int xl = sxl[ix], xh = sxh[ix];
        soff[tid] = make_int4(yl + xl, yl + xh, yh + xl, yh + xh);
    }
    __syncthreads();

    const uint2* __restrict__ base =
        (const uint2*)g_nh + (size_t)b * HW * (NCH/4) + chalf * 32 + lane;

    for (int p = w; p < OPP; p += 8) {
        int ph = p / POUT, pw = p - ph * POUT;
        int t00 = (2*ph) * S14 + 2*pw;
        float f0 = 0.f, f1 = 0.f, f2 = 0.f, f3 = 0.f;
#pragma unroll
        for (int sy = 0; sy < 2; sy++) {
#pragma unroll
            for (int sx = 0; sx < 2; sx++) {
                int   idx = t00 + sy * S14 + sx;
                int4  o   = soff[idx];
                uint4 wt  = swt[idx];

                uint2 q00 = __ldg(base + o.x);
                uint2 q01 = __ldg(base + o.y);
                uint2 q10 = __ldg(base + o.z);
                uint2 q11 = __ldg(base + o.w);

                __half2 t0 = __hmul2(h2(wt.x), h2(q00.x));
                __half2 t1 = __hmul2(h2(wt.x), h2(q00.y));
                t0 = __hfma2(h2(wt.y), h2(q01.x), t0);
                t1 = __hfma2(h2(wt.y), h2(q01.y), t1);
                t0 = __hfma2(h2(wt.z), h2(q10.x), t0);
                t1 = __hfma2(h2(wt.z), h2(q10.y), t1);
                t0 = __hfma2(h2(wt.w), h2(q11.x), t0);
                t1 = __hfma2(h2(wt.w), h2(q11.y), t1);

                float2 a0 = __half22float2(t0);
                float2 a1 = __half22float2(t1);
                f0 += a0.x; f1 += a0.y;
                f2 += a1.x; f3 += a1.y;
            }
        }
        // permuted staging: local channel 4*lane+j -> offset j*32 + lane.
        // STS: lane stride 1 float -> conflict-free.
        float* d = sm + p * SMP + lane;
        d[0]  = f0 * 0.25f;
        d[32] = f1 * 0.25f;
        d[64] = f2 * 0.25f;
        d[96] = f3 * 0.25f;
    }
    __syncthreads();

    // flush: this block owns out[r, chalf*128 .. +128, :] = 6272 contiguous.
    // LDS: p stride 133 == 5 mod 32 (coprime) -> conflict-free.
    float* dst = out + (size_t)r * (NCH * OPP) + (size_t)chalf * (CHB * OPP);
    for (int t = tid; t < CHB * OPP; t += 256) {
        int c = t / OPP;                 // local channel 0..127
        int p = t - c * OPP;
        __stcs(&dst[t], sm[p * SMP + (c & 3) * 32 + (c >> 2)]);
    }
}

extern "C" void kernel_launch(void* const* d_in, const int* in_sizes, int n_in,
                              void* d_out, int out_size)
{
    const float* feat  = (const float*)d_in[0];
    const float* boxes = (const float*)d_in[1];
    float* out = (float*)d_out;

    const int R = out_size / (NCH * OPP);    // 1024

    dim3 tgrid(HW / 32, NCH / 64, 2);        // (1900, 4, 2)
    dim3 tblk(32, 8);
    to_nhwc_h<<<tgrid, tblk>>>(feat);

    dim3 ggrid(R, 2);                        // (1024, 2)
    roi_align_h2t<<<ggrid, 256>>>(boxes, out);
}

// round 11
// speedup vs baseline: 1.3348x; 1.0374x over previous
#include <cuda_runtime.h>
#include <cuda_fp16.h>

// ROI Align via fp16 NHWC relayout (two-kernel, sequential).
//  Pass 1: NCHW fp32 -> NHWC fp16 scratch (62 MB), ldcs streaming reads.
//  Pass 2: block = (ROI, channel-half). 8 warps; warp = output position;
//          lane = 4 channels (uint2). Per-ROI weight/offset tables in smem;
//          per sy-row: 8-term half2 FMA chain, one fp32 convert+add per sy.
//          Conflict-free permuted staging; stcs flush. 5 blocks/SM (natural).

#define NCH   256
#define FH    200
#define FW    304
#define HW    (FH*FW)        // 60800
#define POUT  7
#define OPP   49
#define S14   14
#define CHB   128            // channels per ROI block
#define SMP   133            // staging pitch (floats), 133 mod 32 = 5

__device__ unsigned int g_nh[(size_t)2 * HW * (NCH/2)];   // fp16x2 NHWC, 62 MB

// ---------------- Pass 1: NCHW fp32 -> NHWC fp16 ----------------
__global__ void __launch_bounds__(256)
to_nhwc_h(const float* __restrict__ in)
{
    __shared__ float tile[32][65];
    const int b   = blockIdx.z;
    const int c0  = blockIdx.y * 64;
    const int hw0 = blockIdx.x * 32;
    const int tx  = threadIdx.x;            // 0..31 (hw)
    const int ty  = threadIdx.y;            // 0..7  (c)

    const float* src = in + (size_t)(b * NCH + c0) * HW + hw0;
#pragma unroll
    for (int k = 0; k < 8; k++)
        tile[tx][ty + 8*k] = __ldcs(&src[(size_t)(ty + 8*k) * HW + tx]);
    __syncthreads();

    unsigned int* dst = g_nh + (size_t)(b * HW + hw0) * (NCH/2) + (c0 >> 1);
#pragma unroll
    for (int i = 0; i < 4; i++) {
        int hw = i*8 + ty;
        __half2 h = __floats2half2_rn(tile[hw][2*tx], tile[hw][2*tx + 1]);
        dst[(size_t)hw * (NCH/2) + tx] = *(unsigned int*)&h;
    }
}

// ---------------- Pass 2 ----------------
__device__ __forceinline__ void axis_prep(float t, int size,
                                          int& lo, int& hi, float& frac,
                                          float& valid)
{
    valid = (t > -1.0f && t < (float)size) ? 1.0f : 0.0f;
    float tc  = (t < 0.0f) ? 0.0f : t;
    float low = floorf(tc);
    if (low >= (float)(size - 1)) {
        lo = size - 1; hi = size - 1; frac = 0.0f;
    } else {
        lo = (int)low; hi = lo + 1; frac = tc - low;
    }
}

__device__ __forceinline__ __half2 h2(unsigned int u)
{
    return *reinterpret_cast<const __half2*>(&u);
}

__device__ __forceinline__ unsigned int rep_h2(float f)
{
    __half2 h = __float2half2_rn(f);
    return *reinterpret_cast<unsigned int*>(&h);
}

__global__ void __launch_bounds__(256, 5)
roi_align_h2t(const float* __restrict__ boxes,
              float* __restrict__ out)
{
    __shared__ int   sxl[S14], sxh[S14], syl[S14], syh[S14];  // uint2-granular
    __shared__ float sfx[S14], svx[S14], sfy[S14], svy[S14];
    __shared__ uint4 swt[196];          // 4 replicated-half2 corner weights
    __shared__ int4  soff[196];         // 4 combined corner offsets
    __shared__ float sm[OPP * SMP];     // 26.1 KB staging (permuted layout)

    const int r     = blockIdx.x;
    const int chalf = blockIdx.y;
    const int b     = r >> 9;                // 512 boxes per batch
    const int tid   = threadIdx.x;
    const int lane  = tid & 31;
    const int w     = tid >> 5;

    if (tid < 32) {
        float x1 = boxes[r*4+0] * 0.25f;
        float y1 = boxes[r*4+1] * 0.25f;
        float x2 = boxes[r*4+2] * 0.25f;
        float y2 = boxes[r*4+3] * 0.25f;
        float bw = fmaxf(x2 - x1, 1.0f) * (1.0f/POUT);
        float bh = fmaxf(y2 - y1, 1.0f) * (1.0f/POUT);

        if (tid < S14) {
            float xs = x1 + ((float)tid + 0.5f) * 0.5f * bw;
            int lo, hi; float fr, vd;
            axis_prep(xs, FW, lo, hi, fr, vd);
            sxl[tid] = lo * (NCH/4);          // *64 uint2 per texel
            sxh[tid] = hi * (NCH/4);
            sfx[tid] = fr;  svx[tid] = vd;
        } else if (tid >= 16 && tid < 16 + S14) {
            int i = tid - 16;
            float ys = y1 + ((float)i + 0.5f) * 0.5f * bh;
            int lo, hi; float fr, vd;
            axis_prep(ys, FH, lo, hi, fr, vd);
            syl[i] = lo * FW * (NCH/4);
            syh[i] = hi * FW * (NCH/4);
            sfy[i] = fr;  svy[i] = vd;
        }
    }
    __syncthreads();

    if (tid < 196) {
        int iy = tid / S14;
        int ix = tid - iy * S14;
        float fy = sfy[iy], hy = 1.0f - fy;
        float fx = sfx[ix], hx = 1.0f - fx;
        float vv = svy[iy] * svx[ix];
        swt[tid]  = make_uint4(rep_h2(vv*hy*hx), rep_h2(vv*hy*fx),
                               rep_h2(vv*fy*hx), rep_h2(vv*fy*fx));
        int yl = syl[iy], yh = syh[iy];
        int xl = sxl[ix], xh = sxh[ix];
        soff[tid] = make_int4(yl + xl, yl + xh, yh + xl, yh + xh);
    }
    __syncthreads();

    const uint2* __restrict__ base =
        (const uint2*)g_nh + (size_t)b * HW * (NCH/4) + chalf * 32 + lane;

    for (int p = w; p < OPP; p += 8) {
        int ph = p / POUT, pw = p - ph * POUT;
        int t00 = (2*ph) * S14 + 2*pw;
        float f0 = 0.f, f1 = 0.f, f2 = 0.f, f3 = 0.f;
#pragma unroll
        for (int sy = 0; sy < 2; sy++) {
            int   i0 = t00 + sy * S14;          // (iy, ix0)
            int4  oa = soff[i0];
            int4  ob = soff[i0 + 1];
            uint4 wa = swt[i0];
            uint4 wb = swt[i0 + 1];

            uint2 qa0 = __ldg(base + oa.x);
            uint2 qa1 = __ldg(base + oa.y);
            uint2 qa2 = __ldg(base + oa.z);
            uint2 qa3 = __ldg(base + oa.w);
            uint2 qb0 = __ldg(base + ob.x);
            uint2 qb1 = __ldg(base + ob.y);
            uint2 qb2 = __ldg(base + ob.z);
            uint2 qb3 = __ldg(base + ob.w);

            // 8-term half2 chains (per register pair)
            __half2 t0 = __hmul2(h2(wa.x), h2(qa0.x));
            __half2 t1 = __hmul2(h2(wa.x), h2(qa0.y));
            t0 = __hfma2(h2(wa.y), h2(qa1.x), t0);
            t1 = __hfma2(h2(wa.y), h2(qa1.y), t1);
            t0 = __hfma2(h2(wa.z), h2(qa2.x), t0);
            t1 = __hfma2(h2(wa.z), h2(qa2.y), t1);
            t0 = __hfma2(h2(wa.w), h2(qa3.x), t0);
            t1 = __hfma2(h2(wa.w), h2(qa3.y), t1);
            t0 = __hfma2(h2(wb.x), h2(qb0.x), t0);
            t1 = __hfma2(h2(wb.x), h2(qb0.y), t1);
            t0 = __hfma2(h2(wb.y), h2(qb1.x), t0);
            t1 = __hfma2(h2(wb.y), h2(qb1.y), t1);
            t0 = __hfma2(h2(wb.z), h2(qb2.x), t0);
            t1 = __hfma2(h2(wb.z), h2(qb2.y), t1);
            t0 = __hfma2(h2(wb.w), h2(qb3.x), t0);
            t1 = __hfma2(h2(wb.w), h2(qb3.y), t1);

            float2 a0 = __half22float2(t0);
            float2 a1 = __half22float2(t1);
            f0 += a0.x; f1 += a0.y;
            f2 += a1.x; f3 += a1.y;
        }
        // permuted staging: local channel 4*lane+j -> offset j*32 + lane.
        float* d = sm + p * SMP + lane;
        d[0]  = f0 * 0.25f;
        d[32] = f1 * 0.25f;
        d[64] = f2 * 0.25f;
        d[96] = f3 * 0.25f;
    }
    __syncthreads();

    // flush: out[r, chalf*128 .. +128, :] = 6272 contiguous floats.
    // LDS p-stride 133 ≡ 5 mod 32 -> conflict-free.
    float* dst = out + (size_t)r * (NCH * OPP) + (size_t)chalf * (CHB * OPP);
    for (int t = tid; t < CHB * OPP; t += 256) {
        int c = t / OPP;                 // local channel 0..127
        int p = t - c * OPP;
        __stcs(&dst[t], sm[p * SMP + (c & 3) * 32 + (c >> 2)]);
    }
}

extern "C" void kernel_launch(void* const* d_in, const int* in_sizes, int n_in,
                              void* d_out, int out_size)
{
    const float* feat  = (const float*)d_in[0];
    const float* boxes = (const float*)d_in[1];
    float* out = (float*)d_out;

    const int R = out_size / (NCH * OPP);    // 1024

    dim3 tgrid(HW / 32, NCH / 64, 2);        // (1900, 4, 2)
    dim3 tblk(32, 8);
    to_nhwc_h<<<tgrid, tblk>>>(feat);

    dim3 ggrid(R, 2);                        // (1024, 2)
    roi_align_h2t<<<ggrid, 256>>>(boxes, out);
}